// round 15
// baseline (speedup 1.0000x reference)
#include <cuda_runtime.h>
#include <cuda_bf16.h>

#define BB 128
#define TT 1024
#define VV 192
#define NTHREADS 384
#define NWARPS 12
#define NG 4             // row groups
#define RR 48            // rows per group
#define NC 2             // columns per thread
#define PSTRIDE_B 112    // bytes per p-region (96B bf16 data + pad; quads {0,28,24,20} distinct)
#define NBLK 128         // 128 blocks x 8 steps

__device__ __forceinline__ void hfma2(unsigned& acc, unsigned a, unsigned b) {
    asm("fma.rn.bf16x2 %0, %1, %2, %0;" : "+r"(acc) : "r"(a), "r"(b));
}
__device__ __forceinline__ unsigned pack_bf2(float lo, float hi) {
    unsigned r;
    asm("cvt.rn.bf16x2.f32 %0, %1, %2;" : "=r"(r) : "f"(hi), "f"(lo));
    return r;
}
__device__ __forceinline__ float bf_lo(unsigned v) { return __uint_as_float(v << 16); }
__device__ __forceinline__ float bf_hi(unsigned v) { return __uint_as_float(v & 0xffff0000u); }

__global__ __launch_bounds__(NTHREADS, 1)
void crf_loss_kernel(const float* __restrict__ em,
                     const int* __restrict__ tags,
                     const int* __restrict__ mask,
                     const float* __restrict__ trans,
                     const float* __restrict__ start_t,
                     const float* __restrict__ end_t,
                     float* __restrict__ out)
{
    __shared__ __align__(16) unsigned char s_praw[2][NG * PSTRIDE_B]; // bf16 p, double-buffered
    __shared__ float s_d[2];
    __shared__ unsigned s_mbits[34];
    __shared__ float s_red[NWARPS];
    __shared__ int   s_ired[NWARPS];
    __shared__ float s_num;
    __shared__ float s_seqlen;

    const int b    = blockIdx.x;
    const int tid  = threadIdx.x;
    const int lane = tid & 31;
    const int wid  = tid >> 5;
    const int jb   = tid >> 2;        // 0..95 : block of 2 columns
    const int grp  = tid & 3;         // 0..3  : row group (48 rows)
    const int jown = jb * NC + (grp >> 1);
    const bool writer = ((grp & 1) == 0);
    const bool g1 = (grp & 2);

    const float* emB = em   + (size_t)b * TT * VV;
    const int*   tgB = tags + (size_t)b * TT;
    const int*   mkB = mask + (size_t)b * TT;

    unsigned char* pb0 = &s_praw[0][0];
    unsigned char* pb1 = &s_praw[1][0];
    unsigned char* sts0 = pb0 + (jown / RR) * PSTRIDE_B + (jown % RR) * 2;
    unsigned char* sts1 = pb1 + (jown / RR) * PSTRIDE_B + (jown % RR) * 2;

    // ---------------- expT tile: 2 cols x 48 rows, bf16x2 row-pairs ----------------
    unsigned col2h[NC * 24];
    #pragma unroll
    for (int c = 0; c < NC; c++) {
        const int j = jb * NC + c;
        #pragma unroll
        for (int k = 0; k < 24; k++) {
            const int i = grp * RR + 2 * k;
            float e0 = __expf(trans[(i    ) * VV + j]);
            float e1 = __expf(trans[(i + 1) * VV + j]);
            col2h[c * 24 + k] = pack_bf2(e0, e1);
        }
    }

    // ---------------- mask bitset via ballot ----------------
    for (int w = wid; w < 32; w += NWARPS) {
        int mk = mkB[w * 32 + lane];
        unsigned bal = __ballot_sync(0xffffffffu, mk != 0);
        if (lane == 0) s_mbits[w] = bal;
    }
    if (tid < 2) s_mbits[32 + tid] = 0u;

    // ---------------- gold score + mask sum ----------------
    float gsum = 0.f;
    int   msum = 0;
    for (int t = tid; t < TT; t += NTHREADS) {
        int mk = mkB[t];
        msum += mk;
        if (t >= 1 && mk) {
            int tg = tgB[t];
            int tp = tgB[t - 1];
            gsum += emB[t * VV + tg] + trans[tp * VV + tg];
        }
    }
    #pragma unroll
    for (int o = 16; o > 0; o >>= 1) {
        gsum += __shfl_xor_sync(0xffffffffu, gsum, o);
        msum += __shfl_xor_sync(0xffffffffu, msum, o);
    }
    if (lane == 0) { s_red[wid] = gsum; s_ired[wid] = msum; }
    __syncthreads();
    if (tid == 0) {
        float g = 0.f; int mtot = 0;
        #pragma unroll
        for (int w = 0; w < NWARPS; w++) { g += s_red[w]; mtot += s_ired[w]; }
        int tag0  = tgB[0];
        float num = start_t[tag0] + emB[tag0] + g;
        int last  = mtot - 1; if (last < 0) last = 0;
        num += end_t[tgB[last]];
        s_num    = num;
        s_seqlen = fmaxf((float)mtot, 1.0f);
    }

    // ---------------- init: alpha0, block max M0, p0, sum S0 ----------------
    float a0 = start_t[jown] + emB[jown];
    float wm = a0;
    #pragma unroll
    for (int o = 16; o > 0; o >>= 1)
        wm = fmaxf(wm, __shfl_xor_sync(0xffffffffu, wm, o));
    __syncthreads();                       // protect s_red
    if (lane == 0) s_red[wid] = wm;
    __syncthreads();
    float M = s_red[0];
    #pragma unroll
    for (int w = 1; w < NWARPS; w++) M = fmaxf(M, s_red[w]);

    float p_reg = __expf(a0 - M);
    if (writer) *(__nv_bfloat16*)sts0 = __float2bfloat16(p_reg);

    // sum of p_init -> d0 estimate
    float ssum0 = writer ? p_reg : 0.f;
    #pragma unroll
    for (int o = 16; o > 0; o >>= 1)
        ssum0 += __shfl_xor_sync(0xffffffffu, ssum0, o);
    __syncthreads();
    if (lane == 0) s_red[wid] = ssum0;
    __syncthreads();
    if (tid == 0) {
        float S0 = 0.f;
        #pragma unroll
        for (int w = 0; w < NWARPS; w++) S0 += s_red[w];
        float d0v = __logf(fmaxf(S0, 1e-30f));
        s_d[0] = d0v; s_d[1] = d0v;
    }
    __syncthreads();
    float d_cur = s_d[0];
    float d_nxt = d_cur;

    // tid0 estimator state (tid0 owns column 0, writer)
    float beta_prev = a0 - M;
    float d_meas    = d_cur;

    // mask window (64-bit, covers bits [wbase, wbase+63])
    int wbase = 0;
    unsigned long long mwin =
        (unsigned long long)s_mbits[0] | ((unsigned long long)s_mbits[1] << 32);

    // emission/exp pipeline for step t=1
    int   mk_cur = (int)((mwin >> 1) & 1ull);
    float d_w    = d_cur;
    float w_cur  = __expf(mk_cur ? (emB[VV + jown] - d_w) : (-d_w));
    float e_n1 = emB[2 * VV + jown];       // emit t=2
    float e_n2 = emB[3 * VV + jown];       // emit t=3

    // ---------------- forward recursion: 128 blocks x 8 steps, ONE sync per step ----------------
    #pragma unroll 1
    for (int tb = 0; tb < NBLK; tb++) {
        #pragma unroll
        for (int k = 0; k < 8; k++) {
            const int t = 8 * tb + k + 1;
            unsigned char* pcur = ((t - 1) & 1) ? pb1 : pb0;
            __syncthreads();

            // once-per-block normalizer refresh (tid0, overlaps others' matvec)
            if (k == 0 && tid == 0 && tb >= 1) {
                float beta_now = __logf(fmaxf(p_reg, 1e-35f));
                float g8 = beta_now - beta_prev + 8.f * d_meas;
                s_d[(tb + 1) & 1] = 0.125f * g8 + 0.03125f * beta_now;  // damped AR(2)
                beta_prev = beta_now;
                d_meas = d_cur;
            }

            // 2-col x 48-row bf16 matvec, 4 accumulators (2 per column) for ILP
            const uint4* p4 = (const uint4*)(pcur + grp * PSTRIDE_B);
            unsigned ac0 = 0u, ac0b = 0u, ac1 = 0u, ac1b = 0u;
            #pragma unroll
            for (int q = 0; q < 6; q++) {
                uint4 v = p4[q];
                if (q & 1) {
                    hfma2(ac0b, v.x, col2h[ 0 + 4 * q + 0]); hfma2(ac1b, v.x, col2h[24 + 4 * q + 0]);
                    hfma2(ac0b, v.y, col2h[ 0 + 4 * q + 1]); hfma2(ac1b, v.y, col2h[24 + 4 * q + 1]);
                    hfma2(ac0b, v.z, col2h[ 0 + 4 * q + 2]); hfma2(ac1b, v.z, col2h[24 + 4 * q + 2]);
                    hfma2(ac0b, v.w, col2h[ 0 + 4 * q + 3]); hfma2(ac1b, v.w, col2h[24 + 4 * q + 3]);
                } else {
                    hfma2(ac0,  v.x, col2h[ 0 + 4 * q + 0]); hfma2(ac1,  v.x, col2h[24 + 4 * q + 0]);
                    hfma2(ac0,  v.y, col2h[ 0 + 4 * q + 1]); hfma2(ac1,  v.y, col2h[24 + 4 * q + 1]);
                    hfma2(ac0,  v.z, col2h[ 0 + 4 * q + 2]); hfma2(ac1,  v.z, col2h[24 + 4 * q + 2]);
                    hfma2(ac0,  v.w, col2h[ 0 + 4 * q + 3]); hfma2(ac1,  v.w, col2h[24 + 4 * q + 3]);
                }
            }
            float v0 = (bf_lo(ac0) + bf_hi(ac0)) + (bf_lo(ac0b) + bf_hi(ac0b));
            float v1 = (bf_lo(ac1) + bf_hi(ac1)) + (bf_lo(ac1b) + bf_hi(ac1b));

            // 2-stage butterfly reduce-scatter over the 4 grp-lanes
            // stage 1 (xor 2): grp0,1 keep col0; grp2,3 keep col1
            float x  = g1 ? v0 : v1;
            float r0 = __shfl_xor_sync(0xffffffffu, x, 2);
            float w0 = (g1 ? v1 : v0) + r0;
            // stage 2 (xor 1): full column sum on both partners
            float s  = w0 + __shfl_xor_sync(0xffffffffu, w0, 1);

            float p_new = (mk_cur ? s : p_reg) * w_cur;
            p_reg = p_new;
            M += d_w;
            if (writer) {
                unsigned char* psts = (t & 1) ? sts1 : sts0;
                *(__nv_bfloat16*)psts = __float2bfloat16(p_new);
            }

            // ---- pre-work for step t+1 (before next barrier) ----
            if (k == 6) d_nxt = s_d[(tb + 1) & 1];
            const float d_use = (k == 7) ? d_nxt : d_cur;
            const int tnext = t + 1;
            const int mk_n  = (tnext < TT)
                            ? (int)((mwin >> (unsigned)(tnext - wbase)) & 1ull) : 0;
            d_w   = d_use;
            w_cur = __expf(mk_n ? (e_n1 - d_use) : (-d_use));
            mk_cur = mk_n;
            e_n1 = e_n2;
            {
                int tn = (t + 3 < TT) ? (t + 3) : (TT - 1);
                e_n2 = emB[tn * VV + jown];
            }
            if (k == 7) {
                d_cur = d_nxt;
                int a = (8 * (tb + 1) + 1) >> 5;
                wbase = a << 5;
                mwin = (unsigned long long)s_mbits[a]
                     | ((unsigned long long)s_mbits[a + 1] << 32);
            }
        }
    }

    // ---------------- final lse(alpha + end_trans); alpha = M + log p ----------------
    __syncthreads();
    float beta = __logf(fmaxf(p_reg, 1e-35f));
    float v = writer ? (beta + end_t[jown]) : -3.0e38f;
    float wm2 = v;
    #pragma unroll
    for (int o = 16; o > 0; o >>= 1)
        wm2 = fmaxf(wm2, __shfl_xor_sync(0xffffffffu, wm2, o));
    if (lane == 0) s_red[wid] = wm2;
    __syncthreads();
    float m2 = s_red[0];
    #pragma unroll
    for (int w = 1; w < NWARPS; w++) m2 = fmaxf(m2, s_red[w]);

    float e = writer ? __expf(v - m2) : 0.f;
    #pragma unroll
    for (int o = 16; o > 0; o >>= 1)
        e += __shfl_xor_sync(0xffffffffu, e, o);
    __syncthreads();
    if (lane == 0) s_red[wid] = e;
    __syncthreads();

    if (tid == 0) {
        float ssum = 0.f;
        #pragma unroll
        for (int w = 0; w < NWARPS; w++) ssum += s_red[w];
        float logden = M + m2 + logf(ssum + 1e-8f);
        out[b] = (logden - s_num) / s_seqlen;
    }
}

extern "C" void kernel_launch(void* const* d_in, const int* in_sizes, int n_in,
                              void* d_out, int out_size)
{
    const float* em    = (const float*)d_in[0];
    const int*   tags  = (const int*)d_in[1];
    const int*   mask  = (const int*)d_in[2];
    const float* trans = (const float*)d_in[3];
    const float* st    = (const float*)d_in[4];
    const float* en    = (const float*)d_in[5];
    float* out = (float*)d_out;

    crf_loss_kernel<<<BB, NTHREADS>>>(em, tags, mask, trans, st, en, out);
}

// round 16
// speedup vs baseline: 1.1708x; 1.1708x over previous
#include <cuda_runtime.h>
#include <cuda_bf16.h>

#define BB 128
#define TT 1024
#define VV 192
#define NTHREADS 384
#define NWARPS 12
#define HALFB 192        // bytes per half of p-vector (96 bf16)
#define NBLK 128         // 128 blocks x 8 steps

__device__ __forceinline__ void hfma2(unsigned& acc, unsigned a, unsigned b) {
    asm("fma.rn.bf16x2 %0, %1, %2, %0;" : "+r"(acc) : "r"(a), "r"(b));
}
__device__ __forceinline__ unsigned pack_bf2(float lo, float hi) {
    unsigned r;
    asm("cvt.rn.bf16x2.f32 %0, %1, %2;" : "=r"(r) : "f"(hi), "f"(lo));
    return r;
}
__device__ __forceinline__ float bf_lo(unsigned v) { return __uint_as_float(v << 16); }
__device__ __forceinline__ float bf_hi(unsigned v) { return __uint_as_float(v & 0xffff0000u); }

__global__ __launch_bounds__(NTHREADS, 1)
void crf_loss_kernel(const float* __restrict__ em,
                     const int* __restrict__ tags,
                     const int* __restrict__ mask,
                     const float* __restrict__ trans,
                     const float* __restrict__ start_t,
                     const float* __restrict__ end_t,
                     float* __restrict__ out)
{
    __shared__ __align__(16) unsigned char s_praw[2][2 * HALFB]; // bf16 p vector, double-buffered
    __shared__ float s_d[2];
    __shared__ unsigned s_mbits[34];
    __shared__ float s_red[NWARPS];
    __shared__ int   s_ired[NWARPS];
    __shared__ float s_num;
    __shared__ float s_seqlen;

    const int b    = blockIdx.x;
    const int tid  = threadIdx.x;
    const int lane = tid & 31;
    const int wid  = tid >> 5;
    const int jown = tid >> 1;        // column owned by this lane pair
    const int h    = tid & 1;         // which 96-row half of the column
    const bool writer = (h == 0);

    const float* emB = em   + (size_t)b * TT * VV;
    const int*   tgB = tags + (size_t)b * TT;
    const int*   mkB = mask + (size_t)b * TT;

    unsigned char* pb0 = &s_praw[0][0];
    unsigned char* pb1 = &s_praw[1][0];
    unsigned char* sts0 = pb0 + jown * 2;
    unsigned char* sts1 = pb1 + jown * 2;

    // ---------------- expT half-column: 96 rows, bf16x2 row pairs ----------------
    unsigned col2h[48];
    #pragma unroll
    for (int k = 0; k < 48; k++) {
        const int i = h * 96 + 2 * k;
        float e0 = __expf(trans[(i    ) * VV + jown]);
        float e1 = __expf(trans[(i + 1) * VV + jown]);
        col2h[k] = pack_bf2(e0, e1);
    }

    // ---------------- mask bitset via ballot ----------------
    for (int w = wid; w < 32; w += NWARPS) {
        int mk = mkB[w * 32 + lane];
        unsigned bal = __ballot_sync(0xffffffffu, mk != 0);
        if (lane == 0) s_mbits[w] = bal;
    }
    if (tid < 2) s_mbits[32 + tid] = 0u;

    // ---------------- gold score + mask sum ----------------
    float gsum = 0.f;
    int   msum = 0;
    for (int t = tid; t < TT; t += NTHREADS) {
        int mk = mkB[t];
        msum += mk;
        if (t >= 1 && mk) {
            int tg = tgB[t];
            int tp = tgB[t - 1];
            gsum += emB[t * VV + tg] + trans[tp * VV + tg];
        }
    }
    #pragma unroll
    for (int o = 16; o > 0; o >>= 1) {
        gsum += __shfl_xor_sync(0xffffffffu, gsum, o);
        msum += __shfl_xor_sync(0xffffffffu, msum, o);
    }
    if (lane == 0) { s_red[wid] = gsum; s_ired[wid] = msum; }
    __syncthreads();
    if (tid == 0) {
        float g = 0.f; int mtot = 0;
        #pragma unroll
        for (int w = 0; w < NWARPS; w++) { g += s_red[w]; mtot += s_ired[w]; }
        int tag0  = tgB[0];
        float num = start_t[tag0] + emB[tag0] + g;
        int last  = mtot - 1; if (last < 0) last = 0;
        num += end_t[tgB[last]];
        s_num    = num;
        s_seqlen = fmaxf((float)mtot, 1.0f);
    }

    // ---------------- init: alpha0, block max M0, p0, sum S0 ----------------
    float a0 = start_t[jown] + emB[jown];
    float wm = a0;
    #pragma unroll
    for (int o = 16; o > 0; o >>= 1)
        wm = fmaxf(wm, __shfl_xor_sync(0xffffffffu, wm, o));
    __syncthreads();                       // protect s_red
    if (lane == 0) s_red[wid] = wm;
    __syncthreads();
    float M = s_red[0];
    #pragma unroll
    for (int w = 1; w < NWARPS; w++) M = fmaxf(M, s_red[w]);

    float p_reg = __expf(a0 - M);
    if (writer) *(__nv_bfloat16*)sts0 = __float2bfloat16(p_reg);

    // sum of p_init -> d0 estimate
    float ssum0 = writer ? p_reg : 0.f;
    #pragma unroll
    for (int o = 16; o > 0; o >>= 1)
        ssum0 += __shfl_xor_sync(0xffffffffu, ssum0, o);
    __syncthreads();
    if (lane == 0) s_red[wid] = ssum0;
    __syncthreads();
    if (tid == 0) {
        float S0 = 0.f;
        #pragma unroll
        for (int w = 0; w < NWARPS; w++) S0 += s_red[w];
        float d0v = __logf(fmaxf(S0, 1e-30f));
        s_d[0] = d0v; s_d[1] = d0v;
    }
    __syncthreads();
    float d_cur = s_d[0];
    float d_nxt = d_cur;

    // tid0 estimator state (tid0 owns column 0, writer)
    float beta_prev = a0 - M;
    float d_meas    = d_cur;

    // mask window (64-bit, covers bits [wbase, wbase+63])
    int wbase = 0;
    unsigned long long mwin =
        (unsigned long long)s_mbits[0] | ((unsigned long long)s_mbits[1] << 32);

    // emission/exp pipeline for step t=1
    int   mk_cur = (int)((mwin >> 1) & 1ull);
    float d_w    = d_cur;
    float w_cur  = __expf(mk_cur ? (emB[VV + jown] - d_w) : (-d_w));
    float e_n1 = emB[2 * VV + jown];       // emit t=2
    float e_n2 = emB[3 * VV + jown];       // emit t=3

    // ---------------- forward recursion: 128 blocks x 8 steps, ONE sync per step ----------------
    #pragma unroll 1
    for (int tb = 0; tb < NBLK; tb++) {
        #pragma unroll
        for (int k = 0; k < 8; k++) {
            const int t = 8 * tb + k + 1;
            unsigned char* pcur = ((t - 1) & 1) ? pb1 : pb0;
            __syncthreads();

            // once-per-block normalizer refresh (tid0, overlaps others' matvec)
            if (k == 0 && tid == 0 && tb >= 1) {
                float beta_now = __logf(fmaxf(p_reg, 1e-35f));
                float g8 = beta_now - beta_prev + 8.f * d_meas;
                s_d[(tb + 1) & 1] = 0.125f * g8 + 0.03125f * beta_now;  // damped AR(2)
                beta_prev = beta_now;
                d_meas = d_cur;
            }

            // half-column matvec: 96 rows x 1 col, broadcast LDS (2 addrs/warp)
            const uint4* p4 = (const uint4*)(pcur + h * HALFB);
            unsigned ac0 = 0u, ac1 = 0u, ac2 = 0u, ac3 = 0u;
            #pragma unroll
            for (int q = 0; q < 12; q++) {
                uint4 v = p4[q];
                hfma2(ac0, v.x, col2h[4 * q + 0]);
                hfma2(ac1, v.y, col2h[4 * q + 1]);
                hfma2(ac2, v.z, col2h[4 * q + 2]);
                hfma2(ac3, v.w, col2h[4 * q + 3]);
            }
            float s_half = ((bf_lo(ac0) + bf_hi(ac0)) + (bf_lo(ac1) + bf_hi(ac1)))
                         + ((bf_lo(ac2) + bf_hi(ac2)) + (bf_lo(ac3) + bf_hi(ac3)));
            // single shfl: partner holds the other half of this column
            float s = s_half + __shfl_xor_sync(0xffffffffu, s_half, 1);

            float p_new = (mk_cur ? s : p_reg) * w_cur;
            p_reg = p_new;
            M += d_w;
            if (writer) {
                unsigned char* psts = (t & 1) ? sts1 : sts0;
                *(__nv_bfloat16*)psts = __float2bfloat16(p_new);
            }

            // ---- pre-work for step t+1 (before next barrier) ----
            if (k == 6) d_nxt = s_d[(tb + 1) & 1];
            const float d_use = (k == 7) ? d_nxt : d_cur;
            const int tnext = t + 1;
            const int mk_n  = (tnext < TT)
                            ? (int)((mwin >> (unsigned)(tnext - wbase)) & 1ull) : 0;
            d_w   = d_use;
            w_cur = __expf(mk_n ? (e_n1 - d_use) : (-d_use));
            mk_cur = mk_n;
            e_n1 = e_n2;
            {
                int tn = (t + 3 < TT) ? (t + 3) : (TT - 1);
                e_n2 = emB[tn * VV + jown];
            }
            if (k == 7) {
                d_cur = d_nxt;
                int a = (8 * (tb + 1) + 1) >> 5;
                wbase = a << 5;
                mwin = (unsigned long long)s_mbits[a]
                     | ((unsigned long long)s_mbits[a + 1] << 32);
            }
        }
    }

    // ---------------- final lse(alpha + end_trans); alpha = M + log p ----------------
    __syncthreads();
    float beta = __logf(fmaxf(p_reg, 1e-35f));
    float v = writer ? (beta + end_t[jown]) : -3.0e38f;
    float wm2 = v;
    #pragma unroll
    for (int o = 16; o > 0; o >>= 1)
        wm2 = fmaxf(wm2, __shfl_xor_sync(0xffffffffu, wm2, o));
    if (lane == 0) s_red[wid] = wm2;
    __syncthreads();
    float m2 = s_red[0];
    #pragma unroll
    for (int w = 1; w < NWARPS; w++) m2 = fmaxf(m2, s_red[w]);

    float e = writer ? __expf(v - m2) : 0.f;
    #pragma unroll
    for (int o = 16; o > 0; o >>= 1)
        e += __shfl_xor_sync(0xffffffffu, e, o);
    __syncthreads();
    if (lane == 0) s_red[wid] = e;
    __syncthreads();

    if (tid == 0) {
        float ssum = 0.f;
        #pragma unroll
        for (int w = 0; w < NWARPS; w++) ssum += s_red[w];
        float logden = M + m2 + logf(ssum + 1e-8f);
        out[b] = (logden - s_num) / s_seqlen;
    }
}

extern "C" void kernel_launch(void* const* d_in, const int* in_sizes, int n_in,
                              void* d_out, int out_size)
{
    const float* em    = (const float*)d_in[0];
    const int*   tags  = (const int*)d_in[1];
    const int*   mask  = (const int*)d_in[2];
    const float* trans = (const float*)d_in[3];
    const float* st    = (const float*)d_in[4];
    const float* en    = (const float*)d_in[5];
    float* out = (float*)d_out;

    crf_loss_kernel<<<BB, NTHREADS>>>(em, tags, mask, trans, st, en, out);
}